// round 1
// baseline (speedup 1.0000x reference)
#include <cuda_runtime.h>

// Problem shape (fixed for this dataset; runtime-derived values are checked
// against these and a naive fallback covers any mismatch).
#define NB 10000   // base mesh vertices
#define BB 128     // batch of scalar fields

// Transposed f: fT[n][b], 512B per vertex row. 5.12 MB static device scratch
// (no allocation allowed in kernel_launch).
__device__ float g_fT[NB * BB];

// ---------------------------------------------------------------------------
// Kernel 1: f (B,N) -> fT (N,B), tiled 32x32 smem transpose.
// ---------------------------------------------------------------------------
__global__ void transpose_k(const float* __restrict__ f, int N, int B) {
    __shared__ float s[32][33];
    int nt = blockIdx.x * 32;
    int bt = blockIdx.y * 32;
    int tx = threadIdx.x;
    int ty = threadIdx.y;
#pragma unroll
    for (int i = ty; i < 32; i += 8) {
        int b = bt + i, n = nt + tx;
        s[i][tx] = (n < N && b < B) ? f[b * N + n] : 0.0f;
    }
    __syncthreads();
#pragma unroll
    for (int i = ty; i < 32; i += 8) {
        int n = nt + i, b = bt + tx;
        if (n < N && b < B) g_fT[n * BB + b] = s[tx][i];
    }
}

// ---------------------------------------------------------------------------
// Kernel 2: warp-per-m barycentric gather.
//   Block = 256 threads = 8 warps, block tile = 64 m-values x 128 b.
//   Phase 1: warp w computes m_local = 8w..8w+7. For each m, lane l loads
//            float4 fT[idx][4l..4l+3] (coalesced 512B gather), FMAs 3 weights,
//            stores scalars to smem tile[m_local][b] with pitch 129.
//   Phase 2: tile is drained coalesced along m: thread t writes
//            out[b*M + m0 + (t&63)] for b = (t>>6), (t>>6)+4, ... (32 passes).
//            LDS bank = (129*j + b) % 32 = (j+b) % 32 -> conflict-free.
// ---------------------------------------------------------------------------
__global__ __launch_bounds__(256) void interp_k(
    const int* __restrict__ tri, const float* __restrict__ w,
    float* __restrict__ out, int M) {
    __shared__ float tile[64 * 129];   // 33 KB

    const int m0   = blockIdx.x * 64;
    const int tid  = threadIdx.x;
    const int wid  = tid >> 5;
    const int lane = tid & 31;
    const float4* __restrict__ fT4 = reinterpret_cast<const float4*>(g_fT);

#pragma unroll
    for (int k = 0; k < 8; k++) {
        const int ml = wid * 8 + k;
        const int m  = m0 + ml;
        if (m < M) {
            const int   i0 = __ldg(&tri[3 * m + 0]);
            const int   i1 = __ldg(&tri[3 * m + 1]);
            const int   i2 = __ldg(&tri[3 * m + 2]);
            const float w0 = __ldg(&w[3 * m + 0]);
            const float w1 = __ldg(&w[3 * m + 1]);
            const float w2 = __ldg(&w[3 * m + 2]);

            const float4 a = __ldg(&fT4[i0 * 32 + lane]);
            const float4 b = __ldg(&fT4[i1 * 32 + lane]);
            const float4 c = __ldg(&fT4[i2 * 32 + lane]);

            const int base = ml * 129 + 4 * lane;
            tile[base + 0] = fmaf(w0, a.x, fmaf(w1, b.x, w2 * c.x));
            tile[base + 1] = fmaf(w0, a.y, fmaf(w1, b.y, w2 * c.y));
            tile[base + 2] = fmaf(w0, a.z, fmaf(w1, b.z, w2 * c.z));
            tile[base + 3] = fmaf(w0, a.w, fmaf(w1, b.w, w2 * c.w));
        }
    }
    __syncthreads();

    const int j = tid & 63;
    const int m = m0 + j;
    if (m < M) {
#pragma unroll 8
        for (int b = tid >> 6; b < BB; b += 4) {
            out[(long long)b * M + m] = tile[j * 129 + b];
        }
    }
}

// ---------------------------------------------------------------------------
// Naive fallback (any shape): one thread per m, loop over b.
// ---------------------------------------------------------------------------
__global__ void naive_k(const float* __restrict__ f, const int* __restrict__ tri,
                        const float* __restrict__ w, float* __restrict__ out,
                        int B, int N, int M) {
    int m = blockIdx.x * blockDim.x + threadIdx.x;
    if (m >= M) return;
    const int   i0 = tri[3 * m + 0];
    const int   i1 = tri[3 * m + 1];
    const int   i2 = tri[3 * m + 2];
    const float w0 = w[3 * m + 0];
    const float w1 = w[3 * m + 1];
    const float w2 = w[3 * m + 2];
    for (int b = 0; b < B; b++) {
        const float* fb = f + (long long)b * N;
        out[(long long)b * M + m] =
            fmaf(w0, fb[i0], fmaf(w1, fb[i1], w2 * fb[i2]));
    }
}

extern "C" void kernel_launch(void* const* d_in, const int* in_sizes, int n_in,
                              void* d_out, int out_size) {
    const float* f   = (const float*)d_in[0];
    const int*   tri = (const int*)d_in[1];
    const float* w   = (const float*)d_in[2];
    float*       out = (float*)d_out;

    const int M = in_sizes[1] / 3;          // 500000
    const int B = out_size / M;             // 128
    const int N = in_sizes[0] / B;          // 10000

    if (B == BB && N <= NB) {
        dim3 g1((N + 31) / 32, (B + 31) / 32);
        transpose_k<<<g1, dim3(32, 8)>>>(f, N, B);
        const int blocks = (M + 63) / 64;
        interp_k<<<blocks, 256>>>(tri, w, out, M);
    } else {
        naive_k<<<(M + 127) / 128, 128>>>(f, tri, w, out, B, N, M);
    }
}

// round 2
// speedup vs baseline: 1.1304x; 1.1304x over previous
#include <cuda_runtime.h>

#define NB 10000   // base mesh vertices
#define BB 128     // batch of scalar fields
#define PITCH 132  // smem tile pitch (words): STS bank=lane (conflict-free),
                   // LDS.128 bank-quads distinct per wavefront, 16B-aligned rows

// Transposed f: fT[n][b]. 5.12 MB static device scratch.
__device__ float g_fT[NB * BB];

// ---------------------------------------------------------------------------
// Kernel 1: f (B,N) -> fT (N,B), tiled 32x32 smem transpose.
// ---------------------------------------------------------------------------
__global__ void transpose_k(const float* __restrict__ f, int N, int B) {
    __shared__ float s[32][33];
    int nt = blockIdx.x * 32;
    int bt = blockIdx.y * 32;
    int tx = threadIdx.x;
    int ty = threadIdx.y;
#pragma unroll
    for (int i = ty; i < 32; i += 8) {
        int b = bt + i, n = nt + tx;
        s[i][tx] = (n < N && b < B) ? f[b * N + n] : 0.0f;
    }
    __syncthreads();
#pragma unroll
    for (int i = ty; i < 32; i += 8) {
        int n = nt + i, b = bt + tx;
        if (n < N && b < B) g_fT[n * BB + b] = s[tx][i];
    }
}

// ---------------------------------------------------------------------------
// Kernel 2: warp-per-m barycentric gather, L1-wavefront-minimal version.
//   Block = 256 threads = 8 warps, tile = 64 m x 128 b.
//   Metadata: one 24-lane LDG each for tri/w per warp, broadcast via shfl.
//   Gathers:  per (m, vertex): 4x LDG.32 of 32 contiguous floats
//             (1 wavefront each, cross-LDG rate, no within-LDG replays).
//   STS:      scalar, bank = lane -> conflict-free.
//   Phase 2:  LDS.128 along b + 4 coalesced STG.32 (streaming).
// ---------------------------------------------------------------------------
__global__ __launch_bounds__(256) void interp_k(
    const int* __restrict__ tri, const float* __restrict__ w,
    float* __restrict__ out, int M) {
    __shared__ float tile[64 * PITCH];   // 33 KB

    const int m0   = blockIdx.x * 64;
    const int tid  = threadIdx.x;
    const int wid  = tid >> 5;
    const int lane = tid & 31;
    const int mw   = m0 + wid * 8;       // this warp's first m

    // --- coalesced metadata load: 24 ints + 24 floats per warp ---
    int   ti = 0;
    float wv = 0.0f;
    if (lane < 24 && 3 * mw + lane < 3 * M) {
        ti = __ldg(&tri[3 * mw + lane]);
        wv = __ldg(&w[3 * mw + lane]);
    }

#pragma unroll
    for (int k = 0; k < 8; k++) {
        const int m  = mw + k;
        const int i0 = __shfl_sync(0xffffffffu, ti, 3 * k + 0);
        const int i1 = __shfl_sync(0xffffffffu, ti, 3 * k + 1);
        const int i2 = __shfl_sync(0xffffffffu, ti, 3 * k + 2);
        const float w0 = __shfl_sync(0xffffffffu, wv, 3 * k + 0);
        const float w1 = __shfl_sync(0xffffffffu, wv, 3 * k + 1);
        const float w2 = __shfl_sync(0xffffffffu, wv, 3 * k + 2);
        if (m < M) {
            const float* __restrict__ p0 = g_fT + i0 * BB + lane;
            const float* __restrict__ p1 = g_fT + i1 * BB + lane;
            const float* __restrict__ p2 = g_fT + i2 * BB + lane;
            float* __restrict__ t = &tile[(wid * 8 + k) * PITCH + lane];
#pragma unroll
            for (int c = 0; c < 4; c++) {
                const float a = __ldg(p0 + 32 * c);
                const float b = __ldg(p1 + 32 * c);
                const float d = __ldg(p2 + 32 * c);
                t[32 * c] = fmaf(w0, a, fmaf(w1, b, w2 * d));
            }
        }
    }
    __syncthreads();

    // --- phase 2: coalesced drain along m, vectorized smem reads ---
    const int j = tid & 63;          // m within tile
    const int g = tid >> 6;          // 0..3 -> b-quad group
    const int m = m0 + j;
    if (m < M) {
#pragma unroll
        for (int bb = 0; bb < 8; bb++) {
            const int b = (bb * 4 + g) * 4;               // b-quad start
            const float4 v =
                *reinterpret_cast<const float4*>(&tile[j * PITCH + b]);
            __stcs(&out[(long long)(b + 0) * M + m], v.x);
            __stcs(&out[(long long)(b + 1) * M + m], v.y);
            __stcs(&out[(long long)(b + 2) * M + m], v.z);
            __stcs(&out[(long long)(b + 3) * M + m], v.w);
        }
    }
}

// ---------------------------------------------------------------------------
// Naive fallback (any shape): one thread per m, loop over b.
// ---------------------------------------------------------------------------
__global__ void naive_k(const float* __restrict__ f, const int* __restrict__ tri,
                        const float* __restrict__ w, float* __restrict__ out,
                        int B, int N, int M) {
    int m = blockIdx.x * blockDim.x + threadIdx.x;
    if (m >= M) return;
    const int   i0 = tri[3 * m + 0];
    const int   i1 = tri[3 * m + 1];
    const int   i2 = tri[3 * m + 2];
    const float w0 = w[3 * m + 0];
    const float w1 = w[3 * m + 1];
    const float w2 = w[3 * m + 2];
    for (int b = 0; b < B; b++) {
        const float* fb = f + (long long)b * N;
        out[(long long)b * M + m] =
            fmaf(w0, fb[i0], fmaf(w1, fb[i1], w2 * fb[i2]));
    }
}

extern "C" void kernel_launch(void* const* d_in, const int* in_sizes, int n_in,
                              void* d_out, int out_size) {
    const float* f   = (const float*)d_in[0];
    const int*   tri = (const int*)d_in[1];
    const float* w   = (const float*)d_in[2];
    float*       out = (float*)d_out;

    const int M = in_sizes[1] / 3;          // 500000
    const int B = out_size / M;             // 128
    const int N = in_sizes[0] / B;          // 10000

    if (B == BB && N <= NB) {
        dim3 g1((N + 31) / 32, (B + 31) / 32);
        transpose_k<<<g1, dim3(32, 8)>>>(f, N, B);
        const int blocks = (M + 63) / 64;
        interp_k<<<blocks, 256>>>(tri, w, out, M);
    } else {
        naive_k<<<(M + 127) / 128, 128>>>(f, tri, w, out, B, N, M);
    }
}